// round 16
// baseline (speedup 1.0000x reference)
#include <cuda_runtime.h>
#include <cuda_bf16.h>
#include <cstdint>

#define NN 100000
#define NE 3200000
#define NG 1024
#define CAP 128          // per-node bucket capacity (deg ~ Poisson(32), max ~60)

// ---------------- scratch (device globals; no allocation allowed) ----------
__device__ __align__(256) float g_dis[NN];          // rsqrt(deg)
__device__ __align__(256) float4 g_y4[NN];          // dis*x padded to 4-wide
__device__ __align__(256) float g_ta[NN * 16];      // feature ping
__device__ __align__(256) float g_tb[NN * 16];      // feature pong
__device__ __align__(256) float g_pool[NG * 16];    // pooled (atomic target)
__device__ __align__(256) int g_cnt[NN];            // in-degree (excl self)
__device__ __align__(256) int g_csr[NN * CAP];      // strided bucket CSR
__device__ int g_ei64;
__device__ int g_b64;

// ---------------- index load that tolerates int32 or int64 -----------------
__device__ __forceinline__ int ldidx(const void* p, long long i, int is64) {
    if (is64) return (int)(((const long long*)p)[i]);
    return ((const int*)p)[i];
}

// ---------------- init: zero counters/pool + dtype detection ----------------
__global__ void init_kernel(const void* ei, const void* batch) {
    int i = blockIdx.x * blockDim.x + threadIdx.x;
    if (i < NN) g_cnt[i] = 0;
    if (i < NG * 16) g_pool[i] = 0.0f;
    if (i == 0) {
        const unsigned long long* pe = (const unsigned long long*)ei;
        int big = 0;
        for (int k = 0; k < 8; k++) if (pe[k] > 0xFFFFFFFFull) big = 1;
        g_ei64 = big ? 0 : 1;
        const unsigned long long* pb = (const unsigned long long*)batch;
        int big2 = 0;
        for (int k = 0; k < 8; k++) if (pb[20000 + k] > 0xFFFFFFFFull) big2 = 1;
        g_b64 = big2 ? 0 : 1;
    }
}

// ---------------- single-pass bucket fill; 4 independent edges/thread -------
__global__ void fill_kernel(const void* __restrict__ ei) {
    int t = blockIdx.x * blockDim.x + threadIdx.x;
    const int Q = NE / 4;
    if (t >= Q) return;
    int is64 = g_ei64;
    int s0 = ldidx(ei, t, is64);
    int d0 = ldidx(ei, (long long)NE + t, is64);
    int s1 = ldidx(ei, t + Q, is64);
    int d1 = ldidx(ei, (long long)NE + t + Q, is64);
    int s2 = ldidx(ei, t + 2 * Q, is64);
    int d2 = ldidx(ei, (long long)NE + t + 2 * Q, is64);
    int s3 = ldidx(ei, t + 3 * Q, is64);
    int d3 = ldidx(ei, (long long)NE + t + 3 * Q, is64);
    int p0 = atomicAdd(&g_cnt[d0], 1);
    int p1 = atomicAdd(&g_cnt[d1], 1);
    int p2 = atomicAdd(&g_cnt[d2], 1);
    int p3 = atomicAdd(&g_cnt[d3], 1);
    if (p0 < CAP) g_csr[d0 * CAP + p0] = s0;
    if (p1 < CAP) g_csr[d1 * CAP + p1] = s1;
    if (p2 < CAP) g_csr[d2 * CAP + p2] = s2;
    if (p3 < CAP) g_csr[d3 * CAP + p3] = s3;
}

// ---------------- prep: dis = rsqrt(cnt+1); y = dis*x (padded) --------------
__global__ void prep_kernel(const float* __restrict__ x) {
    int i = blockIdx.x * blockDim.x + threadIdx.x;
    if (i >= NN) return;
    float di = rsqrtf((float)(g_cnt[i] + 1));
    g_dis[i] = di;
    float4 y;
    y.x = di * x[3 * i + 0];
    y.y = di * x[3 * i + 1];
    y.z = di * x[3 * i + 2];
    y.w = 0.0f;
    g_y4[i] = y;
}

// ---------------- fused layer 1: gather y4 + [3->32->16] transform ----------
// EIGHT nodes per warp (4 lanes each), 8 explicit load streams -> MLP=8.
__global__ __launch_bounds__(512) void gather_xform12_kernel(
        const float* __restrict__ W1,
        const float* __restrict__ b1,
        const float* __restrict__ W2) {
    __shared__ float sW1[32 * 3];      // [o*3 + c]
    __shared__ float sb1[32];
    __shared__ float sW2[16 * 33];     // [o*33 + k], padded

    int tid = threadIdx.x;
    if (tid < 96) sW1[tid] = W1[tid];
    if (tid < 32) sb1[tid] = b1[tid];
    for (int idx = tid; idx < 16 * 32; idx += blockDim.x)
        sW2[(idx >> 5) * 33 + (idx & 31)] = W2[idx];
    __syncthreads();

    int warp = (blockIdx.x * blockDim.x + tid) >> 5;
    int sub = (tid >> 2) & 7;          // which of 8 nodes
    int l4 = tid & 3;
    int node = warp * 8 + sub;
    bool valid = node < NN;
    int n = valid ? min(g_cnt[node], CAP) : 0;
    const int* row = g_csr + node * CAP;

    float3 a[8];
#pragma unroll
    for (int q = 0; q < 8; q++) a[q] = make_float3(0.f, 0.f, 0.f);
    for (int e = l4; e < n; e += 32) {
#pragma unroll
        for (int q = 0; q < 8; q++) {
            int ee = e + 4 * q;
            if (ee < n) {
                int s = __ldg(&row[ee]);
                float4 v = __ldg(&g_y4[s]);
                a[q].x += v.x; a[q].y += v.y; a[q].z += v.z;
            }
        }
    }
    float3 acc = make_float3(0.f, 0.f, 0.f);
#pragma unroll
    for (int q = 0; q < 8; q++) { acc.x += a[q].x; acc.y += a[q].y; acc.z += a[q].z; }
#pragma unroll
    for (int s = 2; s > 0; s >>= 1) {     // width-4 reduce
        acc.x += __shfl_xor_sync(0xFFFFFFFFu, acc.x, s, 4);
        acc.y += __shfl_xor_sync(0xFFFFFFFFu, acc.y, s, 4);
        acc.z += __shfl_xor_sync(0xFFFFFFFFu, acc.z, s, 4);
    }
    float di = valid ? g_dis[node] : 0.0f;
    float4 self = valid ? g_y4[node] : make_float4(0.f, 0.f, 0.f, 0.f);
    float p0 = di * (acc.x + self.x);
    float p1 = di * (acc.y + self.y);
    float p2 = di * (acc.z + self.z);
    // 32 h-channels on 4 lanes, 8 each: channel k = l4 + 4*q  (q = 0..7)
    float h[8];
#pragma unroll
    for (int q = 0; q < 8; q++) {
        int o = l4 + 4 * q;
        h[q] = fmaxf(sb1[o]
                     + p0 * sW1[o * 3 + 0]
                     + p1 * sW1[o * 3 + 1]
                     + p2 * sW1[o * 3 + 2], 0.0f);
    }
    // 16 outputs on 4 lanes, 4 each: o = l4 + 4*r
    float v[4] = {0.f, 0.f, 0.f, 0.f};
#pragma unroll
    for (int k = 0; k < 32; k++) {
        float hk = __shfl_sync(0xFFFFFFFFu, h[k >> 2], k & 3, 4);
#pragma unroll
        for (int r = 0; r < 4; r++)
            v[r] += hk * sW2[(l4 + 4 * r) * 33 + k];
    }
    if (valid) {
#pragma unroll
        for (int r = 0; r < 4; r++)
            g_ta[16 * node + l4 + 4 * r] = di * v[r];
    }
}

// ---------------- fused 16-wide gather + combine (+xform | +pool) -----------
// TWO nodes per warp (16 lanes: 4 edge-groups x 4 channel-blocks);
// 8 load streams per lane (32 edges in flight) -> MLP=8.
template <int XFORM>
__global__ __launch_bounds__(512) void gather_combine_kernel(
        const float* __restrict__ tin,
        float* __restrict__ tout,
        const float* __restrict__ b,
        const float* __restrict__ W,
        const void* __restrict__ batch) {
    __shared__ float sb[16];
    __shared__ float sW[16 * 17];      // [o*17 + c], padded
    int tid = threadIdx.x;
    if (tid < 16) sb[tid] = b[tid];
    if (XFORM) {
        for (int idx = tid; idx < 16 * 16; idx += blockDim.x)
            sW[(idx >> 4) * 17 + (idx & 15)] = W[idx];
    }
    __syncthreads();

    int warp = (blockIdx.x * blockDim.x + tid) >> 5;
    int lane = tid & 31;
    int half = lane >> 4;              // which of 2 nodes
    int l16 = lane & 15;
    int grp = l16 >> 2;                // 4 edge groups
    int j = l16 & 3;                   // float4 channel block
    int node = warp * 2 + half;
    bool valid = node < NN;
    int n = valid ? min(g_cnt[node], CAP) : 0;
    const int* row = g_csr + node * CAP;

    float4 a[8];
#pragma unroll
    for (int q = 0; q < 8; q++) a[q] = make_float4(0.f, 0.f, 0.f, 0.f);
    for (int e = grp; e < n; e += 32) {
#pragma unroll
        for (int q = 0; q < 8; q++) {
            int ee = e + 4 * q;
            if (ee < n) {
                int s = __ldg(&row[ee]);
                float4 v = __ldg((const float4*)(tin + 16 * s + 4 * j));
                a[q].x += v.x; a[q].y += v.y; a[q].z += v.z; a[q].w += v.w;
            }
        }
    }
    float4 acc = make_float4(0.f, 0.f, 0.f, 0.f);
#pragma unroll
    for (int q = 0; q < 8; q++) {
        acc.x += a[q].x; acc.y += a[q].y; acc.z += a[q].z; acc.w += a[q].w;
    }
    // reduce across the 4 groups (width-16, strides 4 and 8)
#pragma unroll
    for (int s = 4; s <= 8; s <<= 1) {
        acc.x += __shfl_xor_sync(0xFFFFFFFFu, acc.x, s, 16);
        acc.y += __shfl_xor_sync(0xFFFFFFFFu, acc.y, s, 16);
        acc.z += __shfl_xor_sync(0xFFFFFFFFu, acc.z, s, 16);
        acc.w += __shfl_xor_sync(0xFFFFFFFFu, acc.w, s, 16);
    }
    float di = valid ? g_dis[node] : 0.0f;
    float4 self = valid ? *(const float4*)(tin + 16 * node + 4 * j)
                        : make_float4(0.f, 0.f, 0.f, 0.f);
    float4 h;
    h.x = fmaxf(di * (acc.x + self.x) + sb[4 * j + 0], 0.0f);
    h.y = fmaxf(di * (acc.y + self.y) + sb[4 * j + 1], 0.0f);
    h.z = fmaxf(di * (acc.z + self.z) + sb[4 * j + 2], 0.0f);
    h.w = fmaxf(di * (acc.w + self.w) + sb[4 * j + 3], 0.0f);

    if (XFORM) {
        // t_o = sum_c h_c W[o,c]; channel block jp lives on lane half*16+jp
        int o = l16;
        float v = 0.0f;
#pragma unroll
        for (int jp = 0; jp < 4; jp++) {
            float hx = __shfl_sync(0xFFFFFFFFu, h.x, jp, 16);
            float hy = __shfl_sync(0xFFFFFFFFu, h.y, jp, 16);
            float hz = __shfl_sync(0xFFFFFFFFu, h.z, jp, 16);
            float hw = __shfl_sync(0xFFFFFFFFu, h.w, jp, 16);
            v += hx * sW[o * 17 + 4 * jp + 0]
               + hy * sW[o * 17 + 4 * jp + 1]
               + hz * sW[o * 17 + 4 * jp + 2]
               + hw * sW[o * 17 + 4 * jp + 3];
        }
        if (valid) tout[16 * node + o] = di * v;
    } else {
        if (valid && grp == 0) {       // 4 lanes per node, j = 0..3
            int g = ldidx(batch, node, g_b64);
            float* dst = g_pool + 16 * g + 4 * j;
            asm volatile("red.global.add.v4.f32 [%0], {%1,%2,%3,%4};"
                         :: "l"(dst), "f"(h.x), "f"(h.y), "f"(h.z), "f"(h.w)
                         : "memory");
        }
    }
}

// ---------------- head ------------------------------------------------------
__global__ void head_kernel(const float* __restrict__ We, const float* __restrict__ be,
                            const float* __restrict__ Wc, const float* __restrict__ bc,
                            float* __restrict__ out) {
    int g = blockIdx.x * blockDim.x + threadIdx.x;
    if (g >= NG) return;
    float p[16];
#pragma unroll
    for (int k = 0; k < 16; k++) p[k] = g_pool[g * 16 + k];
    float dot = 0.0f;
#pragma unroll
    for (int o = 0; o < 16; o++) {
        float v = __ldg(&be[o]);
#pragma unroll
        for (int k = 0; k < 16; k++) v += p[k] * __ldg(&We[o * 16 + k]);
        out[g * 16 + o] = v;
        dot += fmaxf(v, 0.0f) * __ldg(&Wc[o]);
    }
    out[NG * 16 + g] = dot + __ldg(&bc[0]);
}

// ---------------- launch ----------------------------------------------------
extern "C" void kernel_launch(void* const* d_in, const int* in_sizes, int n_in,
                              void* d_out, int out_size) {
    const float* x   = (const float*)d_in[0];
    const void*  ei  = d_in[1];
    const void*  bat = d_in[2];
    const float* W1 = (const float*)d_in[3];
    const float* b1 = (const float*)d_in[4];
    const float* W2 = (const float*)d_in[5];
    const float* b2 = (const float*)d_in[6];
    const float* W3 = (const float*)d_in[7];
    const float* b3 = (const float*)d_in[8];
    const float* We = (const float*)d_in[9];
    const float* be = (const float*)d_in[10];
    const float* Wc = (const float*)d_in[11];
    const float* bc = (const float*)d_in[12];
    float* out = (float*)d_out;

    const int TB = 256;
    const int TBW = 512;                                     // gather kernels
    const int gN = (NN + TB - 1) / TB;                       // node grid
    const int gE4 = (NE / 4 + TB - 1) / TB;                  // quarter-edge grid
    const int gW2 = (((NN + 1) / 2) * 32 + TBW - 1) / TBW;   // 2 nodes/warp
    const int gW8 = (((NN + 7) / 8) * 32 + TBW - 1) / TBW;   // 8 nodes/warp

    float *ta = nullptr, *tb = nullptr;
    cudaGetSymbolAddress((void**)&ta, g_ta);    // pure address query, no alloc
    cudaGetSymbolAddress((void**)&tb, g_tb);

    init_kernel<<<gN, TB>>>(ei, bat);
    fill_kernel<<<gE4, TB>>>(ei);               // single edge pass builds buckets
    prep_kernel<<<gN, TB>>>(x);

    gather_xform12_kernel<<<gW8, TBW>>>(W1, b1, W2);              // -> g_ta
    gather_combine_kernel<1><<<gW2, TBW>>>(ta, tb, b2, W3, bat);  // g_ta -> g_tb
    gather_combine_kernel<0><<<gW2, TBW>>>(tb, ta, b3, nullptr, bat); // -> pool

    head_kernel<<<(NG + TB - 1) / TB, TB>>>(We, be, Wc, bc, out);
}

// round 17
// speedup vs baseline: 1.1449x; 1.1449x over previous
#include <cuda_runtime.h>
#include <cuda_bf16.h>
#include <cstdint>

#define NN 100000
#define NE 3200000
#define NG 1024
#define CAP 128          // per-node bucket capacity (deg ~ Poisson(32), max ~60)

// ---------------- scratch (device globals; no allocation allowed) ----------
__device__ __align__(256) float g_dis[NN];          // rsqrt(deg)
__device__ __align__(256) float4 g_y4[NN];          // dis*x padded to 4-wide
__device__ __align__(256) float g_ta[NN * 16];      // feature ping
__device__ __align__(256) float g_tb[NN * 16];      // feature pong
__device__ __align__(256) float g_pool[NG * 16];    // pooled (atomic target)
__device__ __align__(256) int g_cnt[NN];            // in-degree (excl self)
__device__ __align__(256) int g_csr[NN * CAP];      // strided bucket CSR
__device__ int g_ei64;
__device__ int g_b64;

// ---------------- index load that tolerates int32 or int64 -----------------
__device__ __forceinline__ int ldidx(const void* p, long long i, int is64) {
    if (is64) return (int)(((const long long*)p)[i]);
    return ((const int*)p)[i];
}

// ---------------- init: zero counters/pool + dtype detection ----------------
__global__ void init_kernel(const void* ei, const void* batch) {
    int i = blockIdx.x * blockDim.x + threadIdx.x;
    if (i < NN) g_cnt[i] = 0;
    if (i < NG * 16) g_pool[i] = 0.0f;
    if (i == 0) {
        const unsigned long long* pe = (const unsigned long long*)ei;
        int big = 0;
        for (int k = 0; k < 8; k++) if (pe[k] > 0xFFFFFFFFull) big = 1;
        g_ei64 = big ? 0 : 1;
        const unsigned long long* pb = (const unsigned long long*)batch;
        int big2 = 0;
        for (int k = 0; k < 8; k++) if (pb[20000 + k] > 0xFFFFFFFFull) big2 = 1;
        g_b64 = big2 ? 0 : 1;
    }
}

// ---------------- single-pass bucket fill; 4 independent edges/thread -------
__global__ void fill_kernel(const void* __restrict__ ei) {
    int t = blockIdx.x * blockDim.x + threadIdx.x;
    const int Q = NE / 4;
    if (t >= Q) return;
    int is64 = g_ei64;
    int s0 = ldidx(ei, t, is64);
    int d0 = ldidx(ei, (long long)NE + t, is64);
    int s1 = ldidx(ei, t + Q, is64);
    int d1 = ldidx(ei, (long long)NE + t + Q, is64);
    int s2 = ldidx(ei, t + 2 * Q, is64);
    int d2 = ldidx(ei, (long long)NE + t + 2 * Q, is64);
    int s3 = ldidx(ei, t + 3 * Q, is64);
    int d3 = ldidx(ei, (long long)NE + t + 3 * Q, is64);
    int p0 = atomicAdd(&g_cnt[d0], 1);
    int p1 = atomicAdd(&g_cnt[d1], 1);
    int p2 = atomicAdd(&g_cnt[d2], 1);
    int p3 = atomicAdd(&g_cnt[d3], 1);
    if (p0 < CAP) g_csr[d0 * CAP + p0] = s0;
    if (p1 < CAP) g_csr[d1 * CAP + p1] = s1;
    if (p2 < CAP) g_csr[d2 * CAP + p2] = s2;
    if (p3 < CAP) g_csr[d3 * CAP + p3] = s3;
}

// ---------------- prep: dis = rsqrt(cnt+1); y = dis*x (padded) --------------
__global__ void prep_kernel(const float* __restrict__ x) {
    int i = blockIdx.x * blockDim.x + threadIdx.x;
    if (i >= NN) return;
    float di = rsqrtf((float)(g_cnt[i] + 1));
    g_dis[i] = di;
    float4 y;
    y.x = di * x[3 * i + 0];
    y.y = di * x[3 * i + 1];
    y.z = di * x[3 * i + 2];
    y.w = 0.0f;
    g_y4[i] = y;
}

// ---------------- fused layer 1: gather y4 + [3->32->16] transform ----------
// EIGHT nodes per warp (4 lanes each), 8 explicit load streams -> MLP=8.
__global__ void gather_xform12_kernel(const float* __restrict__ W1,
                                      const float* __restrict__ b1,
                                      const float* __restrict__ W2) {
    __shared__ float sW1[32 * 3];      // [o*3 + c]
    __shared__ float sb1[32];
    __shared__ float sW2[16 * 33];     // [o*33 + k], padded

    int tid = threadIdx.x;
    if (tid < 96) sW1[tid] = W1[tid];
    if (tid < 32) sb1[tid] = b1[tid];
    for (int idx = tid; idx < 16 * 32; idx += blockDim.x)
        sW2[(idx >> 5) * 33 + (idx & 31)] = W2[idx];
    __syncthreads();

    int warp = (blockIdx.x * blockDim.x + tid) >> 5;
    int sub = (tid >> 2) & 7;          // which of 8 nodes
    int l4 = tid & 3;
    int node = warp * 8 + sub;
    bool valid = node < NN;
    int n = valid ? min(g_cnt[node], CAP) : 0;
    const int* row = g_csr + node * CAP;

    float3 a[8];
#pragma unroll
    for (int q = 0; q < 8; q++) a[q] = make_float3(0.f, 0.f, 0.f);
    for (int e = l4; e < n; e += 32) {
#pragma unroll
        for (int q = 0; q < 8; q++) {
            int ee = e + 4 * q;
            if (ee < n) {
                int s = __ldg(&row[ee]);
                float4 v = __ldg(&g_y4[s]);
                a[q].x += v.x; a[q].y += v.y; a[q].z += v.z;
            }
        }
    }
    float3 acc = make_float3(0.f, 0.f, 0.f);
#pragma unroll
    for (int q = 0; q < 8; q++) { acc.x += a[q].x; acc.y += a[q].y; acc.z += a[q].z; }
#pragma unroll
    for (int s = 2; s > 0; s >>= 1) {     // width-4 reduce
        acc.x += __shfl_xor_sync(0xFFFFFFFFu, acc.x, s, 4);
        acc.y += __shfl_xor_sync(0xFFFFFFFFu, acc.y, s, 4);
        acc.z += __shfl_xor_sync(0xFFFFFFFFu, acc.z, s, 4);
    }
    float di = valid ? g_dis[node] : 0.0f;
    float4 self = valid ? g_y4[node] : make_float4(0.f, 0.f, 0.f, 0.f);
    float p0 = di * (acc.x + self.x);
    float p1 = di * (acc.y + self.y);
    float p2 = di * (acc.z + self.z);
    // 32 h-channels on 4 lanes, 8 each: channel k = l4 + 4*q  (q = 0..7)
    float h[8];
#pragma unroll
    for (int q = 0; q < 8; q++) {
        int o = l4 + 4 * q;
        h[q] = fmaxf(sb1[o]
                     + p0 * sW1[o * 3 + 0]
                     + p1 * sW1[o * 3 + 1]
                     + p2 * sW1[o * 3 + 2], 0.0f);
    }
    // 16 outputs on 4 lanes, 4 each: o = l4 + 4*r
    float v[4] = {0.f, 0.f, 0.f, 0.f};
#pragma unroll
    for (int k = 0; k < 32; k++) {
        float hk = __shfl_sync(0xFFFFFFFFu, h[k >> 2], k & 3, 4);
#pragma unroll
        for (int r = 0; r < 4; r++)
            v[r] += hk * sW2[(l4 + 4 * r) * 33 + k];
    }
    if (valid) {
#pragma unroll
        for (int r = 0; r < 4; r++)
            g_ta[16 * node + l4 + 4 * r] = di * v[r];
    }
}

// ---------------- fused 16-wide gather + combine (+xform | +pool) -----------
// TWO nodes per warp (16 lanes: 4 edge-groups x 4 channel-blocks);
// 8 load streams per lane (32 edges in flight) -> MLP=8.
template <int XFORM>
__global__ void gather_combine_kernel(const float* __restrict__ tin,
                                      float* __restrict__ tout,
                                      const float* __restrict__ b,
                                      const float* __restrict__ W,
                                      const void* __restrict__ batch) {
    __shared__ float sb[16];
    __shared__ float sW[16 * 17];      // [o*17 + c], padded
    int tid = threadIdx.x;
    if (tid < 16) sb[tid] = b[tid];
    if (XFORM) {
        for (int idx = tid; idx < 16 * 16; idx += blockDim.x)
            sW[(idx >> 4) * 17 + (idx & 15)] = W[idx];
    }
    __syncthreads();

    int warp = (blockIdx.x * blockDim.x + tid) >> 5;
    int lane = tid & 31;
    int half = lane >> 4;              // which of 2 nodes
    int l16 = lane & 15;
    int grp = l16 >> 2;                // 4 edge groups
    int j = l16 & 3;                   // float4 channel block
    int node = warp * 2 + half;
    bool valid = node < NN;
    int n = valid ? min(g_cnt[node], CAP) : 0;
    const int* row = g_csr + node * CAP;

    float4 a[8];
#pragma unroll
    for (int q = 0; q < 8; q++) a[q] = make_float4(0.f, 0.f, 0.f, 0.f);
    for (int e = grp; e < n; e += 32) {
#pragma unroll
        for (int q = 0; q < 8; q++) {
            int ee = e + 4 * q;
            if (ee < n) {
                int s = __ldg(&row[ee]);
                float4 v = __ldg((const float4*)(tin + 16 * s + 4 * j));
                a[q].x += v.x; a[q].y += v.y; a[q].z += v.z; a[q].w += v.w;
            }
        }
    }
    float4 acc = make_float4(0.f, 0.f, 0.f, 0.f);
#pragma unroll
    for (int q = 0; q < 8; q++) {
        acc.x += a[q].x; acc.y += a[q].y; acc.z += a[q].z; acc.w += a[q].w;
    }
    // reduce across the 4 groups (width-16, strides 4 and 8)
#pragma unroll
    for (int s = 4; s <= 8; s <<= 1) {
        acc.x += __shfl_xor_sync(0xFFFFFFFFu, acc.x, s, 16);
        acc.y += __shfl_xor_sync(0xFFFFFFFFu, acc.y, s, 16);
        acc.z += __shfl_xor_sync(0xFFFFFFFFu, acc.z, s, 16);
        acc.w += __shfl_xor_sync(0xFFFFFFFFu, acc.w, s, 16);
    }
    float di = valid ? g_dis[node] : 0.0f;
    float4 self = valid ? *(const float4*)(tin + 16 * node + 4 * j)
                        : make_float4(0.f, 0.f, 0.f, 0.f);
    float4 h;
    h.x = fmaxf(di * (acc.x + self.x) + sb[4 * j + 0], 0.0f);
    h.y = fmaxf(di * (acc.y + self.y) + sb[4 * j + 1], 0.0f);
    h.z = fmaxf(di * (acc.z + self.z) + sb[4 * j + 2], 0.0f);
    h.w = fmaxf(di * (acc.w + self.w) + sb[4 * j + 3], 0.0f);

    if (XFORM) {
        // t_o = sum_c h_c W[o,c]; channel block jp lives on lane half*16+jp
        int o = l16;
        float v = 0.0f;
#pragma unroll
        for (int jp = 0; jp < 4; jp++) {
            float hx = __shfl_sync(0xFFFFFFFFu, h.x, jp, 16);
            float hy = __shfl_sync(0xFFFFFFFFu, h.y, jp, 16);
            float hz = __shfl_sync(0xFFFFFFFFu, h.z, jp, 16);
            float hw = __shfl_sync(0xFFFFFFFFu, h.w, jp, 16);
            v += hx * sW[o * 17 + 4 * jp + 0]
               + hy * sW[o * 17 + 4 * jp + 1]
               + hz * sW[o * 17 + 4 * jp + 2]
               + hw * sW[o * 17 + 4 * jp + 3];
        }
        if (valid) tout[16 * node + o] = di * v;
    } else {
        if (valid && grp == 0) {       // 4 lanes per node, j = 0..3
            int g = ldidx(batch, node, g_b64);
            float* dst = g_pool + 16 * g + 4 * j;
            asm volatile("red.global.add.v4.f32 [%0], {%1,%2,%3,%4};"
                         :: "l"(dst), "f"(h.x), "f"(h.y), "f"(h.z), "f"(h.w)
                         : "memory");
        }
    }
}

// ---------------- head ------------------------------------------------------
__global__ void head_kernel(const float* __restrict__ We, const float* __restrict__ be,
                            const float* __restrict__ Wc, const float* __restrict__ bc,
                            float* __restrict__ out) {
    int g = blockIdx.x * blockDim.x + threadIdx.x;
    if (g >= NG) return;
    float p[16];
#pragma unroll
    for (int k = 0; k < 16; k++) p[k] = g_pool[g * 16 + k];
    float dot = 0.0f;
#pragma unroll
    for (int o = 0; o < 16; o++) {
        float v = __ldg(&be[o]);
#pragma unroll
        for (int k = 0; k < 16; k++) v += p[k] * __ldg(&We[o * 16 + k]);
        out[g * 16 + o] = v;
        dot += fmaxf(v, 0.0f) * __ldg(&Wc[o]);
    }
    out[NG * 16 + g] = dot + __ldg(&bc[0]);
}

// ---------------- launch ----------------------------------------------------
extern "C" void kernel_launch(void* const* d_in, const int* in_sizes, int n_in,
                              void* d_out, int out_size) {
    const float* x   = (const float*)d_in[0];
    const void*  ei  = d_in[1];
    const void*  bat = d_in[2];
    const float* W1 = (const float*)d_in[3];
    const float* b1 = (const float*)d_in[4];
    const float* W2 = (const float*)d_in[5];
    const float* b2 = (const float*)d_in[6];
    const float* W3 = (const float*)d_in[7];
    const float* b3 = (const float*)d_in[8];
    const float* We = (const float*)d_in[9];
    const float* be = (const float*)d_in[10];
    const float* Wc = (const float*)d_in[11];
    const float* bc = (const float*)d_in[12];
    float* out = (float*)d_out;

    const int TB = 256;
    const int gN = (NN + TB - 1) / TB;                      // node grid
    const int gE4 = (NE / 4 + TB - 1) / TB;                 // quarter-edge grid
    const int gW2 = (((NN + 1) / 2) * 32 + TB - 1) / TB;    // 2 nodes/warp
    const int gW8 = (((NN + 7) / 8) * 32 + TB - 1) / TB;    // 8 nodes/warp

    float *ta = nullptr, *tb = nullptr;
    cudaGetSymbolAddress((void**)&ta, g_ta);    // pure address query, no alloc
    cudaGetSymbolAddress((void**)&tb, g_tb);

    init_kernel<<<gN, TB>>>(ei, bat);
    fill_kernel<<<gE4, TB>>>(ei);               // single edge pass builds buckets
    prep_kernel<<<gN, TB>>>(x);

    gather_xform12_kernel<<<gW8, TB>>>(W1, b1, W2);              // -> g_ta
    gather_combine_kernel<1><<<gW2, TB>>>(ta, tb, b2, W3, bat);  // g_ta -> g_tb
    gather_combine_kernel<0><<<gW2, TB>>>(tb, ta, b3, nullptr, bat); // -> pool

    head_kernel<<<(NG + TB - 1) / TB, TB>>>(We, be, Wc, bc, out);
}